// round 12
// baseline (speedup 1.0000x reference)
#include <cuda_runtime.h>
#include <cuda_bf16.h>

#define BB 1024
#define II 256
#define HH 256
#define TT 64
#define TM1 63
#define NG 2          // batch groups (parallel chains)
#define GB (BB / NG)  // 512 batches per group

// ---------------- device scratch (static: no allocation allowed) ----------------
__device__ __nv_bfloat16 g_prefsb[(size_t)BB * TT * II];   // [b][u][i] bf16, 32 MB
__device__ float g_h[2][BB * HH];
__device__ float g_c[2][BB * HH];
__device__ __nv_bfloat16 g_Ahi[2][(size_t)BB * 512];
__device__ __nv_bfloat16 g_Alo[2][(size_t)BB * 512];
__device__ __nv_bfloat16 g_Whi[(size_t)1024 * 512];
__device__ __nv_bfloat16 g_Wlo[(size_t)1024 * 512];
__device__ float g_bias[1024];

// ---------------- helpers ----------------
__device__ __forceinline__ float tanhx(float x) {
    float r; asm("tanh.approx.f32 %0, %1;" : "=f"(r) : "f"(x)); return r;
}
__device__ __forceinline__ float sigm(float x) {
    return 1.0f / (1.0f + __expf(-x));
}
__device__ __forceinline__ void ldm4(unsigned* r, unsigned addr) {
    asm volatile("ldmatrix.sync.aligned.m8n8.x4.shared.b16 {%0,%1,%2,%3}, [%4];"
                 : "=r"(r[0]), "=r"(r[1]), "=r"(r[2]), "=r"(r[3]) : "r"(addr));
}
__device__ __forceinline__ void mma16816(float* d, const unsigned* a, unsigned b0, unsigned b1) {
    asm volatile(
        "mma.sync.aligned.m16n8k16.row.col.f32.bf16.bf16.f32 "
        "{%0,%1,%2,%3}, {%4,%5,%6,%7}, {%8,%9}, {%0,%1,%2,%3};"
        : "+f"(d[0]), "+f"(d[1]), "+f"(d[2]), "+f"(d[3])
        : "r"(a[0]), "r"(a[1]), "r"(a[2]), "r"(a[3]), "r"(b0), "r"(b1));
}
__device__ __forceinline__ void cp16(unsigned saddr, const void* g) {
    asm volatile("cp.async.cg.shared.global [%0], [%1], 16;" :: "r"(saddr), "l"(g));
}
__device__ __forceinline__ void stcs2(float* p, float2 v) {
    asm volatile("st.global.cs.v2.f32 [%0], {%1,%2};" :: "l"(p), "f"(v.x), "f"(v.y));
}
__device__ __forceinline__ void stcs1(float* p, float v) {
    asm volatile("st.global.cs.f32 [%0], %1;" :: "l"(p), "f"(v));
}
__device__ __forceinline__ float2 ldcs2(const float* p) {
    float2 v;
    asm volatile("ld.global.cs.v2.f32 {%0,%1}, [%2];" : "=f"(v.x), "=f"(v.y) : "l"(p));
    return v;
}

// ---------------- init ----------------
__global__ void init_kernel() {
    int idx = blockIdx.x * 256 + threadIdx.x;
    g_h[0][idx] = 0.f;
    g_c[0][idx] = 0.f;
    int b = idx >> 8, j = idx & 255;
    g_Ahi[0][(size_t)b * 512 + 256 + j] = __float2bfloat16(0.f);
    g_Alo[0][(size_t)b * 512 + 256 + j] = __float2bfloat16(0.f);
}

// ---------------- prep: split W into bf16 hi/lo, combine biases ----------------
__global__ void prep_kernel(const float* __restrict__ W_ih, const float* __restrict__ W_hh,
                            const float* __restrict__ b_ih, const float* __restrict__ b_hh) {
    int idx = blockIdx.x * 256 + threadIdx.x;
    int n = idx >> 9, k = idx & 511;
    float v = (k < 256) ? W_ih[n * 256 + k] : W_hh[n * 256 + (k - 256)];
    __nv_bfloat16 hi = __float2bfloat16(v);
    g_Whi[idx] = hi;
    g_Wlo[idx] = __float2bfloat16(v - __bfloat162float(hi));
    if (idx < 1024) g_bias[idx] = b_ih[idx] + b_hh[idx];
}

// ---------------- pre_fs (bf16 out, [b][u][i]) ----------------
__global__ void prefs_kernel(const float* __restrict__ FS,
                             const float* __restrict__ W_fs,
                             const float* __restrict__ b_fs, int b_base) {
    __shared__ float sFS[21 * 256];
    __shared__ float sW[21 * 64];
    __shared__ float sbf[64];
    int b = b_base + blockIdx.x, tid = threadIdx.x;
    if (tid < 64) sbf[tid] = b_fs[tid];
    __syncthreads();
    float acc[64];
#pragma unroll
    for (int u = 0; u < 64; u++) acc[u] = sbf[u];

    for (int cch = 0; cch < 3; cch++) {
        int t0 = cch * 21;
        __syncthreads();
        for (int x = tid; x < 21 * 256; x += 256) sFS[x] = FS[(size_t)b * TM1 * II + t0 * II + x];
        for (int x = tid; x < 21 * 64; x += 256) sW[x] = W_fs[t0 * 64 + x];
        __syncthreads();
        for (int t = 0; t < 21; t++) {
            float xv = sFS[t * 256 + tid];
            const float4* w4 = (const float4*)(sW + t * 64);
#pragma unroll
            for (int j = 0; j < 16; j++) {
                float4 w = w4[j];
                acc[4 * j + 0] += xv * w.x;
                acc[4 * j + 1] += xv * w.y;
                acc[4 * j + 2] += xv * w.z;
                acc[4 * j + 3] += xv * w.w;
            }
        }
    }
#pragma unroll
    for (int u = 0; u < 64; u++)
        g_prefsb[((size_t)b * 64 + u) * 256 + tid] = __float2bfloat16(acc[u]);
}

// ---------------- attention step (R6 shape): 4 batches/block, 512 threads ----------------
__global__ __launch_bounds__(512) void attn_kernel(
        const float* __restrict__ FS, const float* __restrict__ yh,
        const float* __restrict__ W_h, const float* __restrict__ b_h,
        const float* __restrict__ W_fs, const float* __restrict__ W_attn,
        float* __restrict__ out1, int t, int cur, int b_base) {
    __shared__ float hc[4][512];
    __shared__ float sp[8][4][64];
    __shared__ float s_sm[4][64];
    __shared__ float wa[64];
    __shared__ float2 part[4][4][128];   // [u-quarter][batch][i-pair]
    __shared__ float wrm[4][4];
    __shared__ float wrs[4][4];

    int b0 = b_base + blockIdx.x * 4;
    int tid = threadIdx.x;
    const float* hcur = g_h[cur];
    const float* ccur = g_c[cur];

    for (int x = tid; x < 4 * 512; x += 512) {
        int bb = x >> 9, k = x & 511;
        hc[bb][k] = (k < 256) ? hcur[(b0 + bb) * 256 + k] : ccur[(b0 + bb) * 256 + (k - 256)];
    }
    if (tid < 64) wa[tid] = W_attn[tid];
    __syncthreads();

    // phase 1: score_h = [h,c] @ W_h   (u = tid%64, q = tid/64 -> 8 k-chunks of 64)
    {
        int u = tid & 63, q = tid >> 6;
        float p0 = 0, p1 = 0, p2 = 0, p3 = 0;
        int kend = q * 64 + 64;
#pragma unroll 4
        for (int k = q * 64; k < kend; k++) {
            float wv = W_h[k * 64 + u];
            p0 += hc[0][k] * wv; p1 += hc[1][k] * wv;
            p2 += hc[2][k] * wv; p3 += hc[3][k] * wv;
        }
        sp[q][0][u] = p0; sp[q][1][u] = p1; sp[q][2][u] = p2; sp[q][3][u] = p3;
    }
    __syncthreads();
    if (tid < 256) {
        int bb = tid >> 6, uu = tid & 63;
        float y = yh[(b0 + bb) * TM1 + t];
        float s = b_h[uu] + y * W_fs[63 * 64 + uu];
#pragma unroll
        for (int q = 0; q < 8; q++) s += sp[q][bb][uu];
        s_sm[bb][uu] = s;
    }
    __syncthreads();

    // phase 2: partial logits over 16-u quarter, i as bf16x2 pair
    int u4 = tid >> 7, ip = tid & 127;
#pragma unroll
    for (int bb = 0; bb < 4; bb++) {
        const __nv_bfloat162* pf = (const __nv_bfloat162*)
            (g_prefsb + (((size_t)(b0 + bb) * 64 + u4 * 16) << 8)) + ip;
        float ax = 0.f, ay = 0.f;
#pragma unroll
        for (int uu = 0; uu < 16; uu++) {
            float2 p = __bfloat1622float2(pf[uu << 7]);
            float s = s_sm[bb][u4 * 16 + uu];
            float wv = wa[u4 * 16 + uu];
            ax += tanhx(s + p.x) * wv;
            ay += tanhx(s + p.y) * wv;
        }
        part[u4][bb][ip] = make_float2(ax, ay);
    }
    __syncthreads();

    // phase 3: combine quarters, softmax over i, w_in
    {
        int bb = tid >> 7;
        int ipp = tid & 127;
        int lane = tid & 31, wg = (tid >> 5) & 3;
        float2 lg;
        lg.x = part[0][bb][ipp].x + part[1][bb][ipp].x + part[2][bb][ipp].x + part[3][bb][ipp].x;
        lg.y = part[0][bb][ipp].y + part[1][bb][ipp].y + part[2][bb][ipp].y + part[3][bb][ipp].y;
        float m = fmaxf(lg.x, lg.y);
#pragma unroll
        for (int off = 16; off; off >>= 1) m = fmaxf(m, __shfl_xor_sync(0xffffffffu, m, off));
        if (lane == 0) wrm[bb][wg] = m;
        __syncthreads();
        m = fmaxf(fmaxf(wrm[bb][0], wrm[bb][1]), fmaxf(wrm[bb][2], wrm[bb][3]));
        float ex = __expf(lg.x - m), ey = __expf(lg.y - m);
        float s2 = ex + ey;
#pragma unroll
        for (int off = 16; off; off >>= 1) s2 += __shfl_xor_sync(0xffffffffu, s2, off);
        if (lane == 0) wrs[bb][wg] = s2;
        __syncthreads();
        float inv = 1.0f / ((wrs[bb][0] + wrs[bb][1]) + (wrs[bb][2] + wrs[bb][3]));
        int gb = b0 + bb;
        float2 fs = ldcs2(FS + (size_t)gb * TM1 * II + t * II + 2 * ipp);
        float2 w = make_float2(ex * inv * fs.x, ey * inv * fs.y);
        stcs2(out1 + (size_t)gb * TM1 * II + t * II + 2 * ipp, w);
        __nv_bfloat162 hi2, lo2;
        hi2.x = __float2bfloat16(w.x);
        hi2.y = __float2bfloat16(w.y);
        lo2.x = __float2bfloat16(w.x - __bfloat162float(hi2.x));
        lo2.y = __float2bfloat16(w.y - __bfloat162float(hi2.y));
        *(__nv_bfloat162*)(g_Ahi[cur] + (size_t)gb * 512 + 2 * ipp) = hi2;
        *(__nv_bfloat162*)(g_Alo[cur] + (size_t)gb * 512 + 2 * ipp) = lo2;
    }
}

// ---------------- gates GEMM (bf16-split tensor core, cp.async 2-stage) + LSTM ----------------
#define SAP 40
#define ABYTES (128 * SAP * 2)
#define BBYTES (64 * SAP * 2)
#define STAGEB (2 * ABYTES + 2 * BBYTES)
__global__ __launch_bounds__(256) void gates_mma_kernel(float* __restrict__ out2,
                                                        int t, int cur, int b_base) {
    extern __shared__ char dynsm[];
    unsigned sbase = (unsigned)__cvta_generic_to_shared(dynsm);

    int j0 = blockIdx.x * 16;
    int b0 = b_base + blockIdx.y * 128;
    int tid = threadIdx.x;
    int w = tid >> 5, l = tid & 31;
    int lp = l & 7, quad = l >> 3;
    int wrow = w * 16;

    const __nv_bfloat16* Ahi = g_Ahi[cur];
    const __nv_bfloat16* Alo = g_Alo[cur];

    unsigned aoff = (unsigned)(((wrow + lp + (quad & 1) * 8) * SAP + (quad >> 1) * 8) * 2);
    unsigned boff4[4];
#pragma unroll
    for (int q4 = 0; q4 < 4; q4++)
        boff4[q4] = (unsigned)(((q4 * 16 + lp + (quad >> 1) * 8) * SAP + (quad & 1) * 8) * 2);

    int ar0 = tid >> 2, ac4 = tid & 3;
    int br = tid >> 2, bc4 = tid & 3;
    int bng = (br >> 4) * 256 + j0 + (br & 15);

    int colb = (l & 3) * 2;
    float bias[2][2][4];
#pragma unroll
    for (int jb = 0; jb < 2; jb++)
#pragma unroll
        for (int ch = 0; ch < 2; ch++) {
            int j = j0 + jb * 8 + colb + ch;
#pragma unroll
            for (int g = 0; g < 4; g++) bias[jb][ch][g] = g_bias[g * 256 + j];
        }

    float acc[8][4];
#pragma unroll
    for (int nt = 0; nt < 8; nt++)
#pragma unroll
        for (int d = 0; d < 4; d++) acc[nt][d] = 0.f;

    auto issue = [&](int kc, int st) {
        int k0 = kc * 32;
        unsigned so = sbase + st * STAGEB;
#pragma unroll
        for (int it = 0; it < 2; it++) {
            int r = ar0 + it * 64;
            size_t goff = (size_t)(b0 + r) * 512 + k0 + ac4 * 8;
            unsigned sm = so + (unsigned)((r * SAP + ac4 * 8) * 2);
            cp16(sm, Ahi + goff);
            cp16(sm + ABYTES, Alo + goff);
        }
        size_t woff = (size_t)bng * 512 + k0 + bc4 * 8;
        unsigned smb = so + 2 * ABYTES + (unsigned)((br * SAP + bc4 * 8) * 2);
        cp16(smb, g_Whi + woff);
        cp16(smb + BBYTES, g_Wlo + woff);
        asm volatile("cp.async.commit_group;");
    };

    issue(0, 0);
    for (int kc = 0; kc < 16; kc++) {
        int st = kc & 1;
        if (kc + 1 < 16) {
            issue(kc + 1, st ^ 1);
            asm volatile("cp.async.wait_group 1;");
        } else {
            asm volatile("cp.async.wait_group 0;");
        }
        __syncthreads();

        unsigned so = sbase + st * STAGEB;
        unsigned uAhi = so + aoff, uAlo = so + ABYTES + aoff;
#pragma unroll
        for (int ks = 0; ks < 2; ks++) {
            unsigned kb = ks * 32;
            unsigned ahi[4], alo[4];
            ldm4(ahi, uAhi + kb);
            ldm4(alo, uAlo + kb);
            unsigned bh[4][4], bl[4][4];
#pragma unroll
            for (int q4 = 0; q4 < 4; q4++) {
                ldm4(bh[q4], so + 2 * ABYTES + boff4[q4] + kb);
                ldm4(bl[q4], so + 2 * ABYTES + BBYTES + boff4[q4] + kb);
            }
#pragma unroll
            for (int q4 = 0; q4 < 4; q4++) {
                mma16816(acc[2 * q4],     ahi, bh[q4][0], bh[q4][1]);
                mma16816(acc[2 * q4],     ahi, bl[q4][0], bl[q4][1]);
                mma16816(acc[2 * q4],     alo, bh[q4][0], bh[q4][1]);
                mma16816(acc[2 * q4 + 1], ahi, bh[q4][2], bh[q4][3]);
                mma16816(acc[2 * q4 + 1], ahi, bl[q4][2], bl[q4][3]);
                mma16816(acc[2 * q4 + 1], alo, bh[q4][2], bh[q4][3]);
            }
        }
        __syncthreads();
    }

    // epilogue: LSTM in registers
    const float* ccur = g_c[cur];
    float* hnxt = g_h[cur ^ 1];
    float* cnxt = g_c[cur ^ 1];
    __nv_bfloat16* Ahn = g_Ahi[cur ^ 1];
    __nv_bfloat16* Aln = g_Alo[cur ^ 1];
    int row = l >> 2;
#pragma unroll
    for (int jb = 0; jb < 2; jb++)
#pragma unroll
        for (int ch = 0; ch < 2; ch++) {
            int j = j0 + jb * 8 + colb + ch;
#pragma unroll
            for (int rh = 0; rh < 2; rh++) {
                int d = rh * 2 + ch;
                int b = b0 + wrow + row + rh * 8;
                float iv = acc[0 + jb][d] + bias[jb][ch][0];
                float fv = acc[2 + jb][d] + bias[jb][ch][1];
                float gv = acc[4 + jb][d] + bias[jb][ch][2];
                float ov = acc[6 + jb][d] + bias[jb][ch][3];
                int bidx = b * 256 + j;
                float cold = ccur[bidx];
                float cnew = sigm(fv) * cold + sigm(iv) * tanhf(gv);
                float hnew = sigm(ov) * tanhf(cnew);
                cnxt[bidx] = cnew;
                hnxt[bidx] = hnew;
                __nv_bfloat16 hh = __float2bfloat16(hnew);
                Ahn[(size_t)b * 512 + 256 + j] = hh;
                Aln[(size_t)b * 512 + 256 + j] = __float2bfloat16(hnew - __bfloat162float(hh));
                stcs1(out2 + (size_t)b * TM1 * 256 + t * 256 + j, hnew);
            }
        }
}

// ---------------- launch: two independent batch-group chains on two streams ----------------
extern "C" void kernel_launch(void* const* d_in, const int* in_sizes, int n_in,
                              void* d_out, int out_size) {
    const float* FS     = (const float*)d_in[0];
    const float* yh     = (const float*)d_in[1];
    const float* W_h    = (const float*)d_in[2];
    const float* b_h    = (const float*)d_in[3];
    const float* W_fs   = (const float*)d_in[4];
    const float* b_fs   = (const float*)d_in[5];
    const float* W_attn = (const float*)d_in[6];
    // d_in[7] = b_attn: cancels inside softmax, unused
    const float* W_ih   = (const float*)d_in[8];
    const float* W_hh   = (const float*)d_in[9];
    const float* b_ih   = (const float*)d_in[10];
    const float* b_hh   = (const float*)d_in[11];

    float* out1 = (float*)d_out;                       // input_weighted (B, 63, I)
    float* out2 = out1 + (size_t)BB * TM1 * II;        // input_encoded (B, 63, H)

    static cudaStream_t gs[NG];
    static cudaEvent_t ev_fork, ev_join[NG];
    static int once = 0;
    if (!once) {
        cudaFuncSetAttribute(gates_mma_kernel,
                             cudaFuncAttributeMaxDynamicSharedMemorySize, 2 * STAGEB);
        for (int g = 0; g < NG; g++) {
            cudaStreamCreateWithFlags(&gs[g], cudaStreamNonBlocking);
            cudaEventCreateWithFlags(&ev_join[g], cudaEventDisableTiming);
        }
        cudaEventCreateWithFlags(&ev_fork, cudaEventDisableTiming);
        once = 1;
    }

    // prologue on the main (capture) stream
    init_kernel<<<BB * HH / 256, 256>>>();
    prep_kernel<<<1024 * 512 / 256, 256>>>(W_ih, W_hh, b_ih, b_hh);
    cudaEventRecord(ev_fork, 0);

    for (int g = 0; g < NG; g++) {
        int b_base = g * GB;
        cudaStreamWaitEvent(gs[g], ev_fork, 0);
        prefs_kernel<<<GB, 256, 0, gs[g]>>>(FS, W_fs, b_fs, b_base);
        for (int t = 0; t < TM1; t++) {
            int cur = t & 1;
            attn_kernel<<<GB / 4, 512, 0, gs[g]>>>(FS, yh, W_h, b_h, W_fs, W_attn,
                                                   out1, t, cur, b_base);
            gates_mma_kernel<<<dim3(16, GB / 128), 256, 2 * STAGEB, gs[g]>>>(out2, t, cur, b_base);
        }
        cudaEventRecord(ev_join[g], gs[g]);
    }
    for (int g = 0; g < NG; g++) cudaStreamWaitEvent(0, ev_join[g], 0);
}

// round 13
// speedup vs baseline: 1.5514x; 1.5514x over previous
#include <cuda_runtime.h>
#include <cuda_bf16.h>

#define BB 1024
#define II 256
#define HH 256
#define TT 64
#define TM1 63

// ---------------- device scratch (static: no allocation allowed) ----------------
__device__ __nv_bfloat16 g_prefsb[(size_t)BB * TT * II];   // [b][u][i] bf16, 32 MB
__device__ float g_h[2][BB * HH];
__device__ float g_c[2][BB * HH];
__device__ __nv_bfloat16 g_Ahi[2][(size_t)BB * 512];
__device__ __nv_bfloat16 g_Alo[2][(size_t)BB * 512];
__device__ __nv_bfloat16 g_Whi[(size_t)1024 * 512];
__device__ __nv_bfloat16 g_Wlo[(size_t)1024 * 512];
__device__ float g_bias[1024];

// ---------------- helpers ----------------
__device__ __forceinline__ float sigm(float x) {
    return 1.0f / (1.0f + __expf(-x));
}
__device__ __forceinline__ unsigned hadd2b(unsigned a, unsigned b) {
    unsigned d; asm("add.rn.bf16x2 %0, %1, %2;" : "=r"(d) : "r"(a), "r"(b)); return d;
}
__device__ __forceinline__ unsigned tanh2b(unsigned a) {
    unsigned d; asm("tanh.approx.bf16x2 %0, %1;" : "=r"(d) : "r"(a)); return d;
}
__device__ __forceinline__ float b16lo(unsigned q) { return __uint_as_float(q << 16); }
__device__ __forceinline__ float b16hi(unsigned q) { return __uint_as_float(q & 0xFFFF0000u); }
__device__ __forceinline__ unsigned packbf2(float lo, float hi) {
    unsigned d; asm("cvt.rn.bf16x2.f32 %0, %1, %2;" : "=r"(d) : "f"(hi), "f"(lo)); return d;
}
__device__ __forceinline__ void ldm4(unsigned* r, unsigned addr) {
    asm volatile("ldmatrix.sync.aligned.m8n8.x4.shared.b16 {%0,%1,%2,%3}, [%4];"
                 : "=r"(r[0]), "=r"(r[1]), "=r"(r[2]), "=r"(r[3]) : "r"(addr));
}
__device__ __forceinline__ void mma16816(float* d, const unsigned* a, unsigned b0, unsigned b1) {
    asm volatile(
        "mma.sync.aligned.m16n8k16.row.col.f32.bf16.bf16.f32 "
        "{%0,%1,%2,%3}, {%4,%5,%6,%7}, {%8,%9}, {%0,%1,%2,%3};"
        : "+f"(d[0]), "+f"(d[1]), "+f"(d[2]), "+f"(d[3])
        : "r"(a[0]), "r"(a[1]), "r"(a[2]), "r"(a[3]), "r"(b0), "r"(b1));
}
__device__ __forceinline__ void cp16(unsigned saddr, const void* g) {
    asm volatile("cp.async.cg.shared.global [%0], [%1], 16;" :: "r"(saddr), "l"(g));
}
__device__ __forceinline__ void stcs2(float* p, float2 v) {
    asm volatile("st.global.cs.v2.f32 [%0], {%1,%2};" :: "l"(p), "f"(v.x), "f"(v.y));
}
__device__ __forceinline__ void stcs1(float* p, float v) {
    asm volatile("st.global.cs.f32 [%0], %1;" :: "l"(p), "f"(v));
}
__device__ __forceinline__ float2 ldcs2(const float* p) {
    float2 v;
    asm volatile("ld.global.cs.v2.f32 {%0,%1}, [%2];" : "=f"(v.x), "=f"(v.y) : "l"(p));
    return v;
}

// ---------------- init ----------------
__global__ void init_kernel() {
    int idx = blockIdx.x * 256 + threadIdx.x;
    g_h[0][idx] = 0.f;
    g_c[0][idx] = 0.f;
    int b = idx >> 8, j = idx & 255;
    g_Ahi[0][(size_t)b * 512 + 256 + j] = __float2bfloat16(0.f);
    g_Alo[0][(size_t)b * 512 + 256 + j] = __float2bfloat16(0.f);
}

// ---------------- prep: split W into bf16 hi/lo, combine biases ----------------
__global__ void prep_kernel(const float* __restrict__ W_ih, const float* __restrict__ W_hh,
                            const float* __restrict__ b_ih, const float* __restrict__ b_hh) {
    int idx = blockIdx.x * 256 + threadIdx.x;
    int n = idx >> 9, k = idx & 511;
    float v = (k < 256) ? W_ih[n * 256 + k] : W_hh[n * 256 + (k - 256)];
    __nv_bfloat16 hi = __float2bfloat16(v);
    g_Whi[idx] = hi;
    g_Wlo[idx] = __float2bfloat16(v - __bfloat162float(hi));
    if (idx < 1024) g_bias[idx] = b_ih[idx] + b_hh[idx];
}

// ---------------- pre_fs (bf16 out, [b][u][i]) ----------------
__global__ void prefs_kernel(const float* __restrict__ FS,
                             const float* __restrict__ W_fs,
                             const float* __restrict__ b_fs) {
    __shared__ float sFS[21 * 256];
    __shared__ float sW[21 * 64];
    __shared__ float sbf[64];
    int b = blockIdx.x, tid = threadIdx.x;
    if (tid < 64) sbf[tid] = b_fs[tid];
    __syncthreads();
    float acc[64];
#pragma unroll
    for (int u = 0; u < 64; u++) acc[u] = sbf[u];

    for (int cch = 0; cch < 3; cch++) {
        int t0 = cch * 21;
        __syncthreads();
        for (int x = tid; x < 21 * 256; x += 256) sFS[x] = FS[(size_t)b * TM1 * II + t0 * II + x];
        for (int x = tid; x < 21 * 64; x += 256) sW[x] = W_fs[t0 * 64 + x];
        __syncthreads();
        for (int t = 0; t < 21; t++) {
            float xv = sFS[t * 256 + tid];
            const float4* w4 = (const float4*)(sW + t * 64);
#pragma unroll
            for (int j = 0; j < 16; j++) {
                float4 w = w4[j];
                acc[4 * j + 0] += xv * w.x;
                acc[4 * j + 1] += xv * w.y;
                acc[4 * j + 2] += xv * w.z;
                acc[4 * j + 3] += xv * w.w;
            }
        }
    }
#pragma unroll
    for (int u = 0; u < 64; u++)
        g_prefsb[((size_t)b * 64 + u) * 256 + tid] = __float2bfloat16(acc[u]);
}

// ---------------- attention step: R6 shape, packed-bf16 tanh in phase 2 ----------------
__global__ __launch_bounds__(512) void attn_kernel(
        const float* __restrict__ FS, const float* __restrict__ yh,
        const float* __restrict__ W_h, const float* __restrict__ b_h,
        const float* __restrict__ W_fs, const float* __restrict__ W_attn,
        float* __restrict__ out1, int t, int cur) {
    __shared__ float hc[4][512];
    __shared__ float sp[8][4][64];
    __shared__ unsigned s2d[4][64];      // bf16x2 dup of score per (bb, u)
    __shared__ float wa[64];
    __shared__ float2 part[4][4][128];   // [u-quarter][batch][i-pair]
    __shared__ float wrm[4][4];
    __shared__ float wrs[4][4];

    int b0 = blockIdx.x * 4;
    int tid = threadIdx.x;
    const float* hcur = g_h[cur];
    const float* ccur = g_c[cur];

    for (int x = tid; x < 4 * 512; x += 512) {
        int bb = x >> 9, k = x & 511;
        hc[bb][k] = (k < 256) ? hcur[(b0 + bb) * 256 + k] : ccur[(b0 + bb) * 256 + (k - 256)];
    }
    if (tid < 64) wa[tid] = W_attn[tid];
    __syncthreads();

    // phase 1: score_h = [h,c] @ W_h   (u = tid%64, q = tid/64 -> 8 k-chunks of 64)
    {
        int u = tid & 63, q = tid >> 6;
        float p0 = 0, p1 = 0, p2 = 0, p3 = 0;
        int kend = q * 64 + 64;
#pragma unroll 4
        for (int k = q * 64; k < kend; k++) {
            float wv = W_h[k * 64 + u];
            p0 += hc[0][k] * wv; p1 += hc[1][k] * wv;
            p2 += hc[2][k] * wv; p3 += hc[3][k] * wv;
        }
        sp[q][0][u] = p0; sp[q][1][u] = p1; sp[q][2][u] = p2; sp[q][3][u] = p3;
    }
    __syncthreads();
    if (tid < 256) {
        int bb = tid >> 6, uu = tid & 63;
        float y = yh[(b0 + bb) * TM1 + t];
        float s = b_h[uu] + y * W_fs[63 * 64 + uu];
#pragma unroll
        for (int q = 0; q < 8; q++) s += sp[q][bb][uu];
        s2d[bb][uu] = packbf2(s, s);
    }
    __syncthreads();

    // phase 2: partial logits over 16-u quarter, i as bf16x2 pair (packed tanh)
    int u4 = tid >> 7, ip = tid & 127;
#pragma unroll
    for (int bb = 0; bb < 4; bb++) {
        const unsigned* pf = (const unsigned*)
            (g_prefsb + (((size_t)(b0 + bb) * 64 + u4 * 16) << 8)) + ip;
        float ax = 0.f, ay = 0.f;
#pragma unroll
        for (int uu = 0; uu < 16; uu++) {
            int u = u4 * 16 + uu;
            unsigned q = pf[uu << 7];
            unsigned tt = tanh2b(hadd2b(q, s2d[bb][u]));
            float wv = wa[u];
            ax = fmaf(b16lo(tt), wv, ax);
            ay = fmaf(b16hi(tt), wv, ay);
        }
        part[u4][bb][ip] = make_float2(ax, ay);
    }
    __syncthreads();

    // phase 3: combine quarters, softmax over i, w_in
    {
        int bb = tid >> 7;
        int ipp = tid & 127;
        int lane = tid & 31, wg = (tid >> 5) & 3;
        float2 lg;
        lg.x = part[0][bb][ipp].x + part[1][bb][ipp].x + part[2][bb][ipp].x + part[3][bb][ipp].x;
        lg.y = part[0][bb][ipp].y + part[1][bb][ipp].y + part[2][bb][ipp].y + part[3][bb][ipp].y;
        float m = fmaxf(lg.x, lg.y);
#pragma unroll
        for (int off = 16; off; off >>= 1) m = fmaxf(m, __shfl_xor_sync(0xffffffffu, m, off));
        if (lane == 0) wrm[bb][wg] = m;
        __syncthreads();
        m = fmaxf(fmaxf(wrm[bb][0], wrm[bb][1]), fmaxf(wrm[bb][2], wrm[bb][3]));
        float ex = __expf(lg.x - m), ey = __expf(lg.y - m);
        float s2 = ex + ey;
#pragma unroll
        for (int off = 16; off; off >>= 1) s2 += __shfl_xor_sync(0xffffffffu, s2, off);
        if (lane == 0) wrs[bb][wg] = s2;
        __syncthreads();
        float inv = 1.0f / ((wrs[bb][0] + wrs[bb][1]) + (wrs[bb][2] + wrs[bb][3]));
        int gb = b0 + bb;
        float2 fs = ldcs2(FS + (size_t)gb * TM1 * II + t * II + 2 * ipp);
        float2 w = make_float2(ex * inv * fs.x, ey * inv * fs.y);
        stcs2(out1 + (size_t)gb * TM1 * II + t * II + 2 * ipp, w);
        __nv_bfloat162 hi2, lo2;
        hi2.x = __float2bfloat16(w.x);
        hi2.y = __float2bfloat16(w.y);
        lo2.x = __float2bfloat16(w.x - __bfloat162float(hi2.x));
        lo2.y = __float2bfloat16(w.y - __bfloat162float(hi2.y));
        *(__nv_bfloat162*)(g_Ahi[cur] + (size_t)gb * 512 + 2 * ipp) = hi2;
        *(__nv_bfloat162*)(g_Alo[cur] + (size_t)gb * 512 + 2 * ipp) = lo2;
    }
}

// ---------------- gates GEMM (bf16-split tensor core, cp.async 2-stage) + LSTM ----------------
#define SAP 40
#define ABYTES (128 * SAP * 2)
#define BBYTES (64 * SAP * 2)
#define STAGEB (2 * ABYTES + 2 * BBYTES)
__global__ __launch_bounds__(256) void gates_mma_kernel(float* __restrict__ out2, int t, int cur) {
    extern __shared__ char dynsm[];
    unsigned sbase = (unsigned)__cvta_generic_to_shared(dynsm);

    int j0 = blockIdx.x * 16;
    int b0 = blockIdx.y * 128;
    int tid = threadIdx.x;
    int w = tid >> 5, l = tid & 31;
    int lp = l & 7, quad = l >> 3;
    int wrow = w * 16;

    const __nv_bfloat16* Ahi = g_Ahi[cur];
    const __nv_bfloat16* Alo = g_Alo[cur];

    unsigned aoff = (unsigned)(((wrow + lp + (quad & 1) * 8) * SAP + (quad >> 1) * 8) * 2);
    unsigned boff4[4];
#pragma unroll
    for (int q4 = 0; q4 < 4; q4++)
        boff4[q4] = (unsigned)(((q4 * 16 + lp + (quad >> 1) * 8) * SAP + (quad & 1) * 8) * 2);

    int ar0 = tid >> 2, ac4 = tid & 3;
    int br = tid >> 2, bc4 = tid & 3;
    int bng = (br >> 4) * 256 + j0 + (br & 15);

    int colb = (l & 3) * 2;
    float bias[2][2][4];
#pragma unroll
    for (int jb = 0; jb < 2; jb++)
#pragma unroll
        for (int ch = 0; ch < 2; ch++) {
            int j = j0 + jb * 8 + colb + ch;
#pragma unroll
            for (int g = 0; g < 4; g++) bias[jb][ch][g] = g_bias[g * 256 + j];
        }

    float acc[8][4];
#pragma unroll
    for (int nt = 0; nt < 8; nt++)
#pragma unroll
        for (int d = 0; d < 4; d++) acc[nt][d] = 0.f;

    auto issue = [&](int kc, int st) {
        int k0 = kc * 32;
        unsigned so = sbase + st * STAGEB;
#pragma unroll
        for (int it = 0; it < 2; it++) {
            int r = ar0 + it * 64;
            size_t goff = (size_t)(b0 + r) * 512 + k0 + ac4 * 8;
            unsigned sm = so + (unsigned)((r * SAP + ac4 * 8) * 2);
            cp16(sm, Ahi + goff);
            cp16(sm + ABYTES, Alo + goff);
        }
        size_t woff = (size_t)bng * 512 + k0 + bc4 * 8;
        unsigned smb = so + 2 * ABYTES + (unsigned)((br * SAP + bc4 * 8) * 2);
        cp16(smb, g_Whi + woff);
        cp16(smb + BBYTES, g_Wlo + woff);
        asm volatile("cp.async.commit_group;");
    };

    issue(0, 0);
    for (int kc = 0; kc < 16; kc++) {
        int st = kc & 1;
        if (kc + 1 < 16) {
            issue(kc + 1, st ^ 1);
            asm volatile("cp.async.wait_group 1;");
        } else {
            asm volatile("cp.async.wait_group 0;");
        }
        __syncthreads();

        unsigned so = sbase + st * STAGEB;
        unsigned uAhi = so + aoff, uAlo = so + ABYTES + aoff;
#pragma unroll
        for (int ks = 0; ks < 2; ks++) {
            unsigned kb = ks * 32;
            unsigned ahi[4], alo[4];
            ldm4(ahi, uAhi + kb);
            ldm4(alo, uAlo + kb);
            unsigned bh[4][4], bl[4][4];
#pragma unroll
            for (int q4 = 0; q4 < 4; q4++) {
                ldm4(bh[q4], so + 2 * ABYTES + boff4[q4] + kb);
                ldm4(bl[q4], so + 2 * ABYTES + BBYTES + boff4[q4] + kb);
            }
#pragma unroll
            for (int q4 = 0; q4 < 4; q4++) {
                mma16816(acc[2 * q4],     ahi, bh[q4][0], bh[q4][1]);
                mma16816(acc[2 * q4],     ahi, bl[q4][0], bl[q4][1]);
                mma16816(acc[2 * q4],     alo, bh[q4][0], bh[q4][1]);
                mma16816(acc[2 * q4 + 1], ahi, bh[q4][2], bh[q4][3]);
                mma16816(acc[2 * q4 + 1], ahi, bl[q4][2], bl[q4][3]);
                mma16816(acc[2 * q4 + 1], alo, bh[q4][2], bh[q4][3]);
            }
        }
        __syncthreads();
    }

    // epilogue: LSTM in registers
    const float* ccur = g_c[cur];
    float* hnxt = g_h[cur ^ 1];
    float* cnxt = g_c[cur ^ 1];
    __nv_bfloat16* Ahn = g_Ahi[cur ^ 1];
    __nv_bfloat16* Aln = g_Alo[cur ^ 1];
    int row = l >> 2;
#pragma unroll
    for (int jb = 0; jb < 2; jb++)
#pragma unroll
        for (int ch = 0; ch < 2; ch++) {
            int j = j0 + jb * 8 + colb + ch;
#pragma unroll
            for (int rh = 0; rh < 2; rh++) {
                int d = rh * 2 + ch;
                int b = b0 + wrow + row + rh * 8;
                float iv = acc[0 + jb][d] + bias[jb][ch][0];
                float fv = acc[2 + jb][d] + bias[jb][ch][1];
                float gv = acc[4 + jb][d] + bias[jb][ch][2];
                float ov = acc[6 + jb][d] + bias[jb][ch][3];
                int bidx = b * 256 + j;
                float cold = ccur[bidx];
                float cnew = sigm(fv) * cold + sigm(iv) * tanhf(gv);
                float hnew = sigm(ov) * tanhf(cnew);
                cnxt[bidx] = cnew;
                hnxt[bidx] = hnew;
                __nv_bfloat16 hh = __float2bfloat16(hnew);
                Ahn[(size_t)b * 512 + 256 + j] = hh;
                Aln[(size_t)b * 512 + 256 + j] = __float2bfloat16(hnew - __bfloat162float(hh));
                stcs1(out2 + (size_t)b * TM1 * 256 + t * 256 + j, hnew);
            }
        }
}

// ---------------- launch ----------------
extern "C" void kernel_launch(void* const* d_in, const int* in_sizes, int n_in,
                              void* d_out, int out_size) {
    const float* FS     = (const float*)d_in[0];
    const float* yh     = (const float*)d_in[1];
    const float* W_h    = (const float*)d_in[2];
    const float* b_h    = (const float*)d_in[3];
    const float* W_fs   = (const float*)d_in[4];
    const float* b_fs   = (const float*)d_in[5];
    const float* W_attn = (const float*)d_in[6];
    // d_in[7] = b_attn: cancels inside softmax, unused
    const float* W_ih   = (const float*)d_in[8];
    const float* W_hh   = (const float*)d_in[9];
    const float* b_ih   = (const float*)d_in[10];
    const float* b_hh   = (const float*)d_in[11];

    float* out1 = (float*)d_out;                       // input_weighted (B, 63, I)
    float* out2 = out1 + (size_t)BB * TM1 * II;        // input_encoded (B, 63, H)

    static int attr_done = 0;
    if (!attr_done) {
        cudaFuncSetAttribute(gates_mma_kernel,
                             cudaFuncAttributeMaxDynamicSharedMemorySize, 2 * STAGEB);
        attr_done = 1;
    }

    init_kernel<<<BB * HH / 256, 256>>>();
    prep_kernel<<<1024 * 512 / 256, 256>>>(W_ih, W_hh, b_ih, b_hh);
    prefs_kernel<<<BB, 256>>>(FS, W_fs, b_fs);
    for (int t = 0; t < TM1; t++) {
        int cur = t & 1;
        attn_kernel<<<BB / 4, 512>>>(FS, yh, W_h, b_h, W_fs, W_attn, out1, t, cur);
        gates_mma_kernel<<<dim3(16, 8), 256, 2 * STAGEB>>>(out2, t, cur);
    }
}

// round 14
// speedup vs baseline: 1.6254x; 1.0477x over previous
#include <cuda_runtime.h>
#include <cuda_bf16.h>

#define BB 1024
#define II 256
#define HH 256
#define TT 64
#define TM1 63

// ---------------- device scratch (static: no allocation allowed) ----------------
__device__ __nv_bfloat16 g_prefsb[(size_t)BB * TT * II];   // [b][u][i] bf16, 32 MB
__device__ float g_h[2][BB * HH];
__device__ float g_c[2][BB * HH];
__device__ __nv_bfloat16 g_Ahi[2][(size_t)BB * 512];
__device__ __nv_bfloat16 g_Alo[2][(size_t)BB * 512];
__device__ __nv_bfloat16 g_Whi[(size_t)1024 * 512];
__device__ __nv_bfloat16 g_Wlo[(size_t)1024 * 512];
__device__ uint4 g_WhP[64 * 64];          // W_h bf16, [k-octet][u], 8 bf16 per entry
__device__ float g_bias[1024];

// ---------------- helpers ----------------
__device__ __forceinline__ float tanhx(float x) {
    float r; asm("tanh.approx.f32 %0, %1;" : "=f"(r) : "f"(x)); return r;
}
__device__ __forceinline__ float sigm(float x) {
    return 1.0f / (1.0f + __expf(-x));
}
__device__ __forceinline__ float b16lo(unsigned q) { return __uint_as_float(q << 16); }
__device__ __forceinline__ float b16hi(unsigned q) { return __uint_as_float(q & 0xFFFF0000u); }
__device__ __forceinline__ unsigned packbf2(float lo, float hi) {
    unsigned d; asm("cvt.rn.bf16x2.f32 %0, %1, %2;" : "=r"(d) : "f"(hi), "f"(lo)); return d;
}
__device__ __forceinline__ void ldm4(unsigned* r, unsigned addr) {
    asm volatile("ldmatrix.sync.aligned.m8n8.x4.shared.b16 {%0,%1,%2,%3}, [%4];"
                 : "=r"(r[0]), "=r"(r[1]), "=r"(r[2]), "=r"(r[3]) : "r"(addr));
}
__device__ __forceinline__ void mma16816(float* d, const unsigned* a, unsigned b0, unsigned b1) {
    asm volatile(
        "mma.sync.aligned.m16n8k16.row.col.f32.bf16.bf16.f32 "
        "{%0,%1,%2,%3}, {%4,%5,%6,%7}, {%8,%9}, {%0,%1,%2,%3};"
        : "+f"(d[0]), "+f"(d[1]), "+f"(d[2]), "+f"(d[3])
        : "r"(a[0]), "r"(a[1]), "r"(a[2]), "r"(a[3]), "r"(b0), "r"(b1));
}
__device__ __forceinline__ void cp16(unsigned saddr, const void* g) {
    asm volatile("cp.async.cg.shared.global [%0], [%1], 16;" :: "r"(saddr), "l"(g));
}
__device__ __forceinline__ void stcs2(float* p, float2 v) {
    asm volatile("st.global.cs.v2.f32 [%0], {%1,%2};" :: "l"(p), "f"(v.x), "f"(v.y));
}
__device__ __forceinline__ void stcs1(float* p, float v) {
    asm volatile("st.global.cs.f32 [%0], %1;" :: "l"(p), "f"(v));
}
__device__ __forceinline__ float2 ldcs2(const float* p) {
    float2 v;
    asm volatile("ld.global.cs.v2.f32 {%0,%1}, [%2];" : "=f"(v.x), "=f"(v.y) : "l"(p));
    return v;
}

// ---------------- init ----------------
__global__ void init_kernel() {
    int idx = blockIdx.x * 256 + threadIdx.x;
    g_h[0][idx] = 0.f;
    g_c[0][idx] = 0.f;
    int b = idx >> 8, j = idx & 255;
    g_Ahi[0][(size_t)b * 512 + 256 + j] = __float2bfloat16(0.f);
    g_Alo[0][(size_t)b * 512 + 256 + j] = __float2bfloat16(0.f);
}

// ---------------- prep: split W into bf16 hi/lo, pack W_h, combine biases ----------------
__global__ void prep_kernel(const float* __restrict__ W_ih, const float* __restrict__ W_hh,
                            const float* __restrict__ b_ih, const float* __restrict__ b_hh,
                            const float* __restrict__ W_h) {
    int idx = blockIdx.x * 256 + threadIdx.x;
    int n = idx >> 9, k = idx & 511;
    float v = (k < 256) ? W_ih[n * 256 + k] : W_hh[n * 256 + (k - 256)];
    __nv_bfloat16 hi = __float2bfloat16(v);
    g_Whi[idx] = hi;
    g_Wlo[idx] = __float2bfloat16(v - __bfloat162float(hi));
    if (idx < 64 * 64) {
        int o = idx >> 6, u = idx & 63;     // k-octet o: k = 8o..8o+7; W_h is (512, 64)
        uint4 pv;
        pv.x = packbf2(W_h[(8 * o + 0) * 64 + u], W_h[(8 * o + 1) * 64 + u]);
        pv.y = packbf2(W_h[(8 * o + 2) * 64 + u], W_h[(8 * o + 3) * 64 + u]);
        pv.z = packbf2(W_h[(8 * o + 4) * 64 + u], W_h[(8 * o + 5) * 64 + u]);
        pv.w = packbf2(W_h[(8 * o + 6) * 64 + u], W_h[(8 * o + 7) * 64 + u]);
        g_WhP[idx] = pv;
    }
    if (idx < 1024) g_bias[idx] = b_ih[idx] + b_hh[idx];
}

// ---------------- pre_fs (bf16 out, [b][u][i]) ----------------
__global__ void prefs_kernel(const float* __restrict__ FS,
                             const float* __restrict__ W_fs,
                             const float* __restrict__ b_fs) {
    __shared__ float sFS[21 * 256];
    __shared__ float sW[21 * 64];
    __shared__ float sbf[64];
    int b = blockIdx.x, tid = threadIdx.x;
    if (tid < 64) sbf[tid] = b_fs[tid];
    __syncthreads();
    float acc[64];
#pragma unroll
    for (int u = 0; u < 64; u++) acc[u] = sbf[u];

    for (int cch = 0; cch < 3; cch++) {
        int t0 = cch * 21;
        __syncthreads();
        for (int x = tid; x < 21 * 256; x += 256) sFS[x] = FS[(size_t)b * TM1 * II + t0 * II + x];
        for (int x = tid; x < 21 * 64; x += 256) sW[x] = W_fs[t0 * 64 + x];
        __syncthreads();
        for (int t = 0; t < 21; t++) {
            float xv = sFS[t * 256 + tid];
            const float4* w4 = (const float4*)(sW + t * 64);
#pragma unroll
            for (int j = 0; j < 16; j++) {
                float4 w = w4[j];
                acc[4 * j + 0] += xv * w.x;
                acc[4 * j + 1] += xv * w.y;
                acc[4 * j + 2] += xv * w.z;
                acc[4 * j + 3] += xv * w.w;
            }
        }
    }
#pragma unroll
    for (int u = 0; u < 64; u++)
        g_prefsb[((size_t)b * 64 + u) * 256 + tid] = __float2bfloat16(acc[u]);
}

// ---------------- attention step: R6 shape; phase 1 uses packed bf16 W_h ----------------
__global__ __launch_bounds__(512) void attn_kernel(
        const float* __restrict__ FS, const float* __restrict__ yh,
        const float* __restrict__ b_h,
        const float* __restrict__ W_fs, const float* __restrict__ W_attn,
        float* __restrict__ out1, int t, int cur) {
    __shared__ float hc[4][512];
    __shared__ float sp[8][4][64];
    __shared__ float s_sm[4][64];
    __shared__ float wa[64];
    __shared__ float2 part[4][4][128];   // [u-quarter][batch][i-pair]
    __shared__ float wrm[4][4];
    __shared__ float wrs[4][4];

    int b0 = blockIdx.x * 4;
    int tid = threadIdx.x;
    const float* hcur = g_h[cur];
    const float* ccur = g_c[cur];

    for (int x = tid; x < 4 * 512; x += 512) {
        int bb = x >> 9, k = x & 511;
        hc[bb][k] = (k < 256) ? hcur[(b0 + bb) * 256 + k] : ccur[(b0 + bb) * 256 + (k - 256)];
    }
    if (tid < 64) wa[tid] = W_attn[tid];
    __syncthreads();

    // phase 1: score_h = [h,c] @ W_h   (u = tid%64, q = tid/64 -> 64-k chunk)
    // packed bf16 W_h: 8 uint4 loads per thread, lanes coalesced over u
    {
        int u = tid & 63, q = tid >> 6;
        const uint4* wp = g_WhP + q * 8 * 64 + u;
        float p0 = 0, p1 = 0, p2 = 0, p3 = 0;
#pragma unroll
        for (int ch = 0; ch < 8; ch++) {
            uint4 wv = wp[ch * 64];
            unsigned wq[4] = {wv.x, wv.y, wv.z, wv.w};
#pragma unroll
            for (int e = 0; e < 4; e++) {
                int k = q * 64 + ch * 8 + e * 2;
                float wlo = b16lo(wq[e]), whi = b16hi(wq[e]);
                p0 = fmaf(hc[0][k], wlo, p0); p0 = fmaf(hc[0][k + 1], whi, p0);
                p1 = fmaf(hc[1][k], wlo, p1); p1 = fmaf(hc[1][k + 1], whi, p1);
                p2 = fmaf(hc[2][k], wlo, p2); p2 = fmaf(hc[2][k + 1], whi, p2);
                p3 = fmaf(hc[3][k], wlo, p3); p3 = fmaf(hc[3][k + 1], whi, p3);
            }
        }
        sp[q][0][u] = p0; sp[q][1][u] = p1; sp[q][2][u] = p2; sp[q][3][u] = p3;
    }
    __syncthreads();
    if (tid < 256) {
        int bb = tid >> 6, uu = tid & 63;
        float y = yh[(b0 + bb) * TM1 + t];
        float s = b_h[uu] + y * W_fs[63 * 64 + uu];
#pragma unroll
        for (int q = 0; q < 8; q++) s += sp[q][bb][uu];
        s_sm[bb][uu] = s;
    }
    __syncthreads();

    // phase 2: partial logits over 16-u quarter, i as bf16x2 pair (f32 tanh, R6-proven)
    int u4 = tid >> 7, ip = tid & 127;
#pragma unroll
    for (int bb = 0; bb < 4; bb++) {
        const __nv_bfloat162* pf = (const __nv_bfloat162*)
            (g_prefsb + (((size_t)(b0 + bb) * 64 + u4 * 16) << 8)) + ip;
        float ax = 0.f, ay = 0.f;
#pragma unroll
        for (int uu = 0; uu < 16; uu++) {
            float2 p = __bfloat1622float2(pf[uu << 7]);
            float s = s_sm[bb][u4 * 16 + uu];
            float wv = wa[u4 * 16 + uu];
            ax += tanhx(s + p.x) * wv;
            ay += tanhx(s + p.y) * wv;
        }
        part[u4][bb][ip] = make_float2(ax, ay);
    }
    __syncthreads();

    // phase 3: combine quarters, softmax over i, w_in
    {
        int bb = tid >> 7;
        int ipp = tid & 127;
        int lane = tid & 31, wg = (tid >> 5) & 3;
        float2 lg;
        lg.x = part[0][bb][ipp].x + part[1][bb][ipp].x + part[2][bb][ipp].x + part[3][bb][ipp].x;
        lg.y = part[0][bb][ipp].y + part[1][bb][ipp].y + part[2][bb][ipp].y + part[3][bb][ipp].y;
        float m = fmaxf(lg.x, lg.y);
#pragma unroll
        for (int off = 16; off; off >>= 1) m = fmaxf(m, __shfl_xor_sync(0xffffffffu, m, off));
        if (lane == 0) wrm[bb][wg] = m;
        __syncthreads();
        m = fmaxf(fmaxf(wrm[bb][0], wrm[bb][1]), fmaxf(wrm[bb][2], wrm[bb][3]));
        float ex = __expf(lg.x - m), ey = __expf(lg.y - m);
        float s2 = ex + ey;
#pragma unroll
        for (int off = 16; off; off >>= 1) s2 += __shfl_xor_sync(0xffffffffu, s2, off);
        if (lane == 0) wrs[bb][wg] = s2;
        __syncthreads();
        float inv = 1.0f / ((wrs[bb][0] + wrs[bb][1]) + (wrs[bb][2] + wrs[bb][3]));
        int gb = b0 + bb;
        float2 fs = ldcs2(FS + (size_t)gb * TM1 * II + t * II + 2 * ipp);
        float2 w = make_float2(ex * inv * fs.x, ey * inv * fs.y);
        stcs2(out1 + (size_t)gb * TM1 * II + t * II + 2 * ipp, w);
        __nv_bfloat162 hi2, lo2;
        hi2.x = __float2bfloat16(w.x);
        hi2.y = __float2bfloat16(w.y);
        lo2.x = __float2bfloat16(w.x - __bfloat162float(hi2.x));
        lo2.y = __float2bfloat16(w.y - __bfloat162float(hi2.y));
        *(__nv_bfloat162*)(g_Ahi[cur] + (size_t)gb * 512 + 2 * ipp) = hi2;
        *(__nv_bfloat162*)(g_Alo[cur] + (size_t)gb * 512 + 2 * ipp) = lo2;
    }
}

// ---------------- gates GEMM (bf16-split tensor core, cp.async 2-stage) + LSTM ----------------
#define SAP 40
#define ABYTES (128 * SAP * 2)
#define BBYTES (64 * SAP * 2)
#define STAGEB (2 * ABYTES + 2 * BBYTES)
__global__ __launch_bounds__(256) void gates_mma_kernel(float* __restrict__ out2, int t, int cur) {
    extern __shared__ char dynsm[];
    unsigned sbase = (unsigned)__cvta_generic_to_shared(dynsm);

    int j0 = blockIdx.x * 16;
    int b0 = blockIdx.y * 128;
    int tid = threadIdx.x;
    int w = tid >> 5, l = tid & 31;
    int lp = l & 7, quad = l >> 3;
    int wrow = w * 16;

    const __nv_bfloat16* Ahi = g_Ahi[cur];
    const __nv_bfloat16* Alo = g_Alo[cur];

    unsigned aoff = (unsigned)(((wrow + lp + (quad & 1) * 8) * SAP + (quad >> 1) * 8) * 2);
    unsigned boff4[4];
#pragma unroll
    for (int q4 = 0; q4 < 4; q4++)
        boff4[q4] = (unsigned)(((q4 * 16 + lp + (quad >> 1) * 8) * SAP + (quad & 1) * 8) * 2);

    int ar0 = tid >> 2, ac4 = tid & 3;
    int br = tid >> 2, bc4 = tid & 3;
    int bng = (br >> 4) * 256 + j0 + (br & 15);

    int colb = (l & 3) * 2;
    float bias[2][2][4];
#pragma unroll
    for (int jb = 0; jb < 2; jb++)
#pragma unroll
        for (int ch = 0; ch < 2; ch++) {
            int j = j0 + jb * 8 + colb + ch;
#pragma unroll
            for (int g = 0; g < 4; g++) bias[jb][ch][g] = g_bias[g * 256 + j];
        }

    float acc[8][4];
#pragma unroll
    for (int nt = 0; nt < 8; nt++)
#pragma unroll
        for (int d = 0; d < 4; d++) acc[nt][d] = 0.f;

    auto issue = [&](int kc, int st) {
        int k0 = kc * 32;
        unsigned so = sbase + st * STAGEB;
#pragma unroll
        for (int it = 0; it < 2; it++) {
            int r = ar0 + it * 64;
            size_t goff = (size_t)(b0 + r) * 512 + k0 + ac4 * 8;
            unsigned sm = so + (unsigned)((r * SAP + ac4 * 8) * 2);
            cp16(sm, Ahi + goff);
            cp16(sm + ABYTES, Alo + goff);
        }
        size_t woff = (size_t)bng * 512 + k0 + bc4 * 8;
        unsigned smb = so + 2 * ABYTES + (unsigned)((br * SAP + bc4 * 8) * 2);
        cp16(smb, g_Whi + woff);
        cp16(smb + BBYTES, g_Wlo + woff);
        asm volatile("cp.async.commit_group;");
    };

    issue(0, 0);
    for (int kc = 0; kc < 16; kc++) {
        int st = kc & 1;
        if (kc + 1 < 16) {
            issue(kc + 1, st ^ 1);
            asm volatile("cp.async.wait_group 1;");
        } else {
            asm volatile("cp.async.wait_group 0;");
        }
        __syncthreads();

        unsigned so = sbase + st * STAGEB;
        unsigned uAhi = so + aoff, uAlo = so + ABYTES + aoff;
#pragma unroll
        for (int ks = 0; ks < 2; ks++) {
            unsigned kb = ks * 32;
            unsigned ahi[4], alo[4];
            ldm4(ahi, uAhi + kb);
            ldm4(alo, uAlo + kb);
            unsigned bh[4][4], bl[4][4];
#pragma unroll
            for (int q4 = 0; q4 < 4; q4++) {
                ldm4(bh[q4], so + 2 * ABYTES + boff4[q4] + kb);
                ldm4(bl[q4], so + 2 * ABYTES + BBYTES + boff4[q4] + kb);
            }
#pragma unroll
            for (int q4 = 0; q4 < 4; q4++) {
                mma16816(acc[2 * q4],     ahi, bh[q4][0], bh[q4][1]);
                mma16816(acc[2 * q4],     ahi, bl[q4][0], bl[q4][1]);
                mma16816(acc[2 * q4],     alo, bh[q4][0], bh[q4][1]);
                mma16816(acc[2 * q4 + 1], ahi, bh[q4][2], bh[q4][3]);
                mma16816(acc[2 * q4 + 1], ahi, bl[q4][2], bl[q4][3]);
                mma16816(acc[2 * q4 + 1], alo, bh[q4][2], bh[q4][3]);
            }
        }
        __syncthreads();
    }

    // epilogue: LSTM in registers
    const float* ccur = g_c[cur];
    float* hnxt = g_h[cur ^ 1];
    float* cnxt = g_c[cur ^ 1];
    __nv_bfloat16* Ahn = g_Ahi[cur ^ 1];
    __nv_bfloat16* Aln = g_Alo[cur ^ 1];
    int row = l >> 2;
#pragma unroll
    for (int jb = 0; jb < 2; jb++)
#pragma unroll
        for (int ch = 0; ch < 2; ch++) {
            int j = j0 + jb * 8 + colb + ch;
#pragma unroll
            for (int rh = 0; rh < 2; rh++) {
                int d = rh * 2 + ch;
                int b = b0 + wrow + row + rh * 8;
                float iv = acc[0 + jb][d] + bias[jb][ch][0];
                float fv = acc[2 + jb][d] + bias[jb][ch][1];
                float gv = acc[4 + jb][d] + bias[jb][ch][2];
                float ov = acc[6 + jb][d] + bias[jb][ch][3];
                int bidx = b * 256 + j;
                float cold = ccur[bidx];
                float cnew = sigm(fv) * cold + sigm(iv) * tanhf(gv);
                float hnew = sigm(ov) * tanhf(cnew);
                cnxt[bidx] = cnew;
                hnxt[bidx] = hnew;
                __nv_bfloat16 hh = __float2bfloat16(hnew);
                Ahn[(size_t)b * 512 + 256 + j] = hh;
                Aln[(size_t)b * 512 + 256 + j] = __float2bfloat16(hnew - __bfloat162float(hh));
                stcs1(out2 + (size_t)b * TM1 * 256 + t * 256 + j, hnew);
            }
        }
}

// ---------------- launch ----------------
extern "C" void kernel_launch(void* const* d_in, const int* in_sizes, int n_in,
                              void* d_out, int out_size) {
    const float* FS     = (const float*)d_in[0];
    const float* yh     = (const float*)d_in[1];
    const float* W_h    = (const float*)d_in[2];
    const float* b_h    = (const float*)d_in[3];
    const float* W_fs   = (const float*)d_in[4];
    const float* b_fs   = (const float*)d_in[5];
    const float* W_attn = (const float*)d_in[6];
    // d_in[7] = b_attn: cancels inside softmax, unused
    const float* W_ih   = (const float*)d_in[8];
    const float* W_hh   = (const float*)d_in[9];
    const float* b_ih   = (const float*)d_in[10];
    const float* b_hh   = (const float*)d_in[11];

    float* out1 = (float*)d_out;                       // input_weighted (B, 63, I)
    float* out2 = out1 + (size_t)BB * TM1 * II;        // input_encoded (B, 63, H)

    static int attr_done = 0;
    if (!attr_done) {
        cudaFuncSetAttribute(gates_mma_kernel,
                             cudaFuncAttributeMaxDynamicSharedMemorySize, 2 * STAGEB);
        attr_done = 1;
    }

    init_kernel<<<BB * HH / 256, 256>>>();
    prep_kernel<<<1024 * 512 / 256, 256>>>(W_ih, W_hh, b_ih, b_hh, W_h);
    prefs_kernel<<<BB, 256>>>(FS, W_fs, b_fs);
    for (int t = 0; t < TM1; t++) {
        int cur = t & 1;
        attn_kernel<<<BB / 4, 512>>>(FS, yh, b_h, W_fs, W_attn, out1, t, cur);
        gates_mma_kernel<<<dim3(16, 8), 256, 2 * STAGEB>>>(out2, t, cur);
    }
}